// round 6
// baseline (speedup 1.0000x reference)
#include <cuda_runtime.h>
#include <math_constants.h>

// Problem constants (match reference setup_inputs)
#define NUM_STATES 10000
#define BATCH      64
#define SEQLEN     4096
#define TPB        256
#define CHUNKS     (SEQLEN / TPB)   // 16
#define GRID       (BATCH * CHUNKS) // 1024

// Scratch (device globals per harness rules)
__device__ float        g_partials[GRID];
__device__ unsigned int g_counter = 0;

// Random 4B gather with 64B L2 fetch-granularity hint (instead of default 128B).
__device__ __forceinline__ float ldg_l2_64(const float* p)
{
    float v;
    asm volatile("ld.global.nc.L2::64B.f32 %0, [%1];" : "=f"(v) : "l"(p));
    return v;
}

__global__ __launch_bounds__(TPB)
void markov_fused_kernel(const int*   __restrict__ seqs,
                         const int*   __restrict__ lengths,
                         const float* __restrict__ initial,
                         const float* __restrict__ trans,
                         float*       __restrict__ out)
{
    const int b     = blockIdx.x >> 4;        // sequence id (16 chunks per sequence)
    const int chunk = blockIdx.x & 15;
    const int tid   = threadIdx.x;
    const int t     = chunk * TPB + tid + 1;  // transition target index, 1..4096
    const int len   = lengths[b];
    const int* s    = seqs + b * SEQLEN;

    // Predicated gather: skip the DRAM line fetch entirely for invalid t.
    float v = 0.0f;
    if (t < len) {
        const int sp = s[t - 1];
        const int sc = s[t];
        const float p = ldg_l2_64(&trans[(size_t)sp * NUM_STATES + sc]);
        v = __logf(p);
    }

    // ---- block reduction (warp shuffle + shared) ----
    #pragma unroll
    for (int off = 16; off > 0; off >>= 1)
        v += __shfl_down_sync(0xffffffff, v, off);

    __shared__ float warp_sums[TPB / 32];
    const int lane = tid & 31;
    const int wid  = tid >> 5;
    if (lane == 0) warp_sums[wid] = v;
    __syncthreads();

    if (wid == 0) {
        v = (lane < TPB / 32) ? warp_sums[lane] : 0.0f;
        #pragma unroll
        for (int off = 4; off > 0; off >>= 1)
            v += __shfl_down_sync(0xffffffff, v, off);
        if (lane == 0)
            g_partials[blockIdx.x] = v;   // seq b's partials at [16b .. 16b+15]
    }

    // ---- last-block-done finalize (single launch, deterministic) ----
    __shared__ bool isLast;
    if (tid == 0) {
        __threadfence();
        const unsigned int done = atomicAdd(&g_counter, 1u);
        isLast = (done == GRID - 1);
    }
    __syncthreads();
    if (!isLast) return;

    float ll = 0.0f;
    if (tid < BATCH) {
        ll = __logf(__ldg(&initial[__ldg(&seqs[tid * SEQLEN])]));
        #pragma unroll
        for (int c = 0; c < CHUNKS; c++)
            ll += g_partials[tid * CHUNKS + c];
    }

    __shared__ float sll[BATCH];
    if (tid < BATCH) sll[tid] = ll;
    __syncthreads();

    if (tid == 0) {
        float m = -CUDART_INF_F;
        #pragma unroll 8
        for (int i = 0; i < BATCH; i++)
            m = fmaxf(m, sll[i]);
        float ssum = 0.0f;
        #pragma unroll 8
        for (int i = 0; i < BATCH; i++)
            ssum += __expf(sll[i] - m);
        out[0] = -(m + __logf(ssum));
        g_counter = 0;   // reset for next graph replay (determinism)
    }
}

extern "C" void kernel_launch(void* const* d_in, const int* in_sizes, int n_in,
                              void* d_out, int out_size)
{
    const int*   seqs    = (const int*)d_in[0];
    const int*   lengths = (const int*)d_in[1];
    const float* initial = (const float*)d_in[2];
    const float* trans   = (const float*)d_in[3];
    float*       out     = (float*)d_out;

    markov_fused_kernel<<<GRID, TPB>>>(seqs, lengths, initial, trans, out);
}